// round 13
// baseline (speedup 1.0000x reference)
#include <cuda_runtime.h>
#include <cuda_fp16.h>
#include <stdint.h>

#define DIN      4096
#define ROWS_X   8192
#define ROWS_W   4096
#define NSTAGES  3
#define NCHUNK   32                              // 4096 int8 / 128 per chunk
#define TILE_M   128
#define TILE_N   128
#define A_STAGE_BYTES (TILE_M*128)               // 16 KB
#define B_STAGE_BYTES (TILE_N*128)               // 16 KB
#define STAGE_BYTES   (A_STAGE_BYTES + B_STAGE_BYTES)
#define SMEM_GEMM     (NSTAGES*STAGE_BYTES + 1024)

__device__ __align__(16) char g_X16[(size_t)ROWS_X * DIN];   // 32 MB int8
__device__ __align__(16) char g_W16[(size_t)ROWS_W * DIN];   // 16 MB int8
__device__ float g_partials[256];
__device__ float g_wscale;

// ---------- helpers ----------
static __device__ __forceinline__ uint32_t smem_u32(const void* p) {
    uint32_t a;
    asm("{ .reg .u64 t; cvta.to.shared.u64 t, %1; cvt.u32.u64 %0, t; }" : "=r"(a) : "l"(p));
    return a;
}
static __device__ __forceinline__ void cp16(uint32_t dst, const void* src) {
    asm volatile("cp.async.cg.shared.global [%0], [%1], 16;" :: "r"(dst), "l"(src) : "memory");
}
static __device__ __forceinline__ void ldmx4(uint32_t* r, uint32_t addr) {
    asm volatile("ldmatrix.sync.aligned.m8n8.x4.shared.b16 {%0,%1,%2,%3}, [%4];"
                 : "=r"(r[0]), "=r"(r[1]), "=r"(r[2]), "=r"(r[3]) : "r"(addr));
}
// s8 IMMA, s32 accum; fragments occupy the same bytes as the f16-k16 layout.
static __device__ __forceinline__ void mma16832(int* d, const uint32_t* a,
                                                uint32_t b0, uint32_t b1) {
    asm volatile(
        "mma.sync.aligned.m16n8k32.row.col.s32.s8.s8.s32 "
        "{%0,%1,%2,%3}, {%4,%5,%6,%7}, {%8,%9}, {%0,%1,%2,%3};"
        : "+r"(d[0]), "+r"(d[1]), "+r"(d[2]), "+r"(d[3])
        : "r"(a[0]), "r"(a[1]), "r"(a[2]), "r"(a[3]), "r"(b0), "r"(b1));
}
static __device__ __forceinline__ uint32_t sw(uint32_t off) {
    return off ^ ((off >> 3) & 0x70);
}

// radix-16 in-register Hadamard butterfly (float)
static __device__ __forceinline__ void bfly16(float* v) {
    #pragma unroll
    for (int b = 0; b < 4; b++) {
        const int m = 1 << b;
        #pragma unroll
        for (int k = 0; k < 16; k++) {
            if (!(k & m)) {
                float a = v[k], c = v[k ^ m];
                v[k] = a + c; v[k ^ m] = a - c;
            }
        }
    }
}
static __device__ __forceinline__ int P16(int i) { return i + (i >> 4); }

// block-wide reduction, NW warps
template <int OP, int NW>
static __device__ __forceinline__ float block_red(float v, float* red, int tid) {
    #pragma unroll
    for (int o = 16; o > 0; o >>= 1) {
        float t = __shfl_xor_sync(0xFFFFFFFFu, v, o);
        v = (OP == 0) ? (v + t) : fmaxf(v, t);
    }
    if ((tid & 31) == 0) red[tid >> 5] = v;
    __syncthreads();
    float r = red[0];
    #pragma unroll
    for (int i = 1; i < NW; i++)
        r = (OP == 0) ? (r + red[i]) : fmaxf(r, red[i]);
    __syncthreads();
    return r;
}

// ---------- kernel 1: |w| partial sums (deterministic) ----------
__global__ void __launch_bounds__(256) wabs_part(const float* __restrict__ w) {
    __shared__ float red[256];
    const int tid = threadIdx.x;
    const size_t s0 = (size_t)blockIdx.x * 65536;
    float s = 0.f;
    for (int i = tid; i < 65536; i += 256) s += fabsf(w[s0 + i]);
    red[tid] = s; __syncthreads();
    for (int o = 128; o > 0; o >>= 1) { if (tid < o) red[tid] += red[tid + o]; __syncthreads(); }
    if (tid == 0) g_partials[blockIdx.x] = red[0];
}

static __device__ __forceinline__ float wscale_from_partials(float* red) {
    const int tid = threadIdx.x;
    if (tid < 256) red[tid] = g_partials[tid];
    __syncthreads();
    #pragma unroll
    for (int o = 128; o > 0; o >>= 1) {
        if (tid < o) red[tid] += red[tid + o];
        __syncthreads();
    }
    return red[0] * (1.0f / 16777216.0f);
}

// ---------- kernel 2: ternarize + FWHT over d-bits 4..11 -> int8 W16 ----------
__global__ void __launch_bounds__(256) w_fwht(const float* __restrict__ w) {
    __shared__ float s[4096 + 256];
    const int t = threadIdx.x;
    const float* wr = w + (size_t)blockIdx.x * DIN;
    const float wscale = wscale_from_partials(s);
    const float thr = 0.5f * wscale;
    if (blockIdx.x == 0 && t == 0) g_wscale = wscale;
    __syncthreads();

    float v[16];
    #pragma unroll
    for (int q = 0; q < 4; q++) {
        float4 p = *reinterpret_cast<const float4*>(wr + t * 16 + q * 4);
        v[q*4+0]=p.x; v[q*4+1]=p.y; v[q*4+2]=p.z; v[q*4+3]=p.w;
    }
    #pragma unroll
    for (int k = 0; k < 16; k++)
        v[k] = (v[k] > thr) ? 1.0f : ((v[k] < -thr) ? -1.0f : 0.0f);
    // NO bfly on bits 0-3 (H16 lives on the X side)
    #pragma unroll
    for (int k = 0; k < 16; k++) s[P16(t * 16 + k)] = v[k];
    __syncthreads();

    const int base = (t & 15) + (t >> 4) * 256;
    #pragma unroll
    for (int k = 0; k < 16; k++) v[k] = s[P16(base + 16 * k)];
    bfly16(v);                              // d bits 4-7
    #pragma unroll
    for (int k = 0; k < 16; k++) s[P16(base + 16 * k)] = v[k];
    __syncthreads();

    #pragma unroll
    for (int k = 0; k < 16; k++) v[k] = s[P16(t + 256 * k)];
    bfly16(v);                              // d bits 8-11
    char* dst = g_W16 + (size_t)blockIdx.x * DIN;
    #pragma unroll
    for (int k = 0; k < 16; k++) {
        float q = fminf(fmaxf(v[k], -127.0f), 127.0f);   // 9.2-sigma clamp, P~1e-13
        dst[t + 256 * k] = (char)(int)q;
    }
}

// ---------- kernel 3: LayerNorm + absmax quantize + H16 (d-bits 0..3) -> int8 X16 ----
__global__ void __launch_bounds__(256) ln_quant(const float* __restrict__ x,
                                                const float* __restrict__ gamma,
                                                const float* __restrict__ beta) {
    __shared__ float red8[8];
    const int tid = threadIdx.x;
    const float* xr = x + (size_t)blockIdx.x * DIN;
    const int c0 = tid * 16;

    float v[16];
    #pragma unroll
    for (int q = 0; q < 4; q++) {
        float4 p = *reinterpret_cast<const float4*>(xr + c0 + q * 4);
        v[q*4+0]=p.x; v[q*4+1]=p.y; v[q*4+2]=p.z; v[q*4+3]=p.w;
    }
    float s = 0.f;
    #pragma unroll
    for (int i = 0; i < 16; i++) s += v[i];
    const float mu = block_red<0,8>(s, red8, tid) * (1.0f / DIN);

    float sq = 0.f;
    #pragma unroll
    for (int i = 0; i < 16; i++) { float d = v[i] - mu; sq += d * d; }
    const float rstd = 1.0f / sqrtf(block_red<0,8>(sq, red8, tid) * (1.0f / DIN) + 1e-5f);

    float y[16];
    float amax = 0.f;
    #pragma unroll
    for (int q = 0; q < 4; q++) {
        float4 gg = *reinterpret_cast<const float4*>(gamma + c0 + q * 4);
        float4 bb = *reinterpret_cast<const float4*>(beta  + c0 + q * 4);
        float gv[4] = {gg.x, gg.y, gg.z, gg.w};
        float bv[4] = {bb.x, bb.y, bb.z, bb.w};
        #pragma unroll
        for (int i = 0; i < 4; i++) {
            y[q*4+i] = (v[q*4+i] - mu) * rstd * gv[i] + bv[i];
            amax = fmaxf(amax, fabsf(y[q*4+i]));
        }
    }
    const float scale = fminf(fmaxf(block_red<1,8>(amax, red8, tid), 1e-6f), 1e6f);
    const float sf = fminf(fmaxf(7.0f / scale, 1e-6f), 1e6f);

    float q16[16];
    #pragma unroll
    for (int i = 0; i < 16; i++)
        q16[i] = fminf(fmaxf(rintf(y[i] * sf), -7.0f), 7.0f);
    bfly16(q16);                            // d bits 0-3 (|v| <= 112, int8-exact)

    char h[16];
    #pragma unroll
    for (int i = 0; i < 16; i++) h[i] = (char)(int)q16[i];
    *reinterpret_cast<uint4*>(g_X16 + (size_t)blockIdx.x * DIN + c0) =
        *reinterpret_cast<uint4*>(h);
}

// ---------- kernel 4: INT8 IMMA GEMM + fine o-FWHT (bits 0..5) + scale ----------
__global__ void __launch_bounds__(128, 2) gemm_kernel(float* __restrict__ out) {
    extern __shared__ char smem_raw[];
    const uint32_t data_base = (smem_u32(smem_raw) + 1023u) & ~1023u;
    const int tid = threadIdx.x;
    const int wid = tid >> 5;
    const int lid = tid & 31;
    const int wm = wid >> 1;        // 0..1 (64-row slab)
    const int wn = wid & 1;         // 0..1 (64-col slab)
    const int tileN = blockIdx.x;   // 0..31
    const int tileM = blockIdx.y;   // 0..63

    const char* Ag = g_X16 + (size_t)tileM * TILE_M * DIN;
    const char* Bg = g_W16 + (size_t)tileN * TILE_N * DIN;

    auto load_chunk = [&](int c, int stage) {
        const uint32_t abase = data_base + stage * STAGE_BYTES;
        const uint32_t bbase = abase + A_STAGE_BYTES;
        #pragma unroll
        for (int t = 0; t < 8; t++) {
            int idx = tid + t * 128;
            int r = idx >> 3, j = idx & 7;
            uint32_t off = (uint32_t)(r * 128 + j * 16);
            cp16(abase + sw(off), Ag + (size_t)r * DIN + c * 128 + j * 16);
        }
        #pragma unroll
        for (int t = 0; t < 8; t++) {
            int idx = tid + t * 128;
            int r = idx >> 3, j = idx & 7;
            uint32_t off = (uint32_t)(r * 128 + j * 16);
            cp16(bbase + sw(off), Bg + (size_t)r * DIN + c * 128 + j * 16);
        }
    };

    int acc[4][8][4];
    #pragma unroll
    for (int i = 0; i < 4; i++)
        #pragma unroll
        for (int j = 0; j < 8; j++)
            #pragma unroll
            for (int q = 0; q < 4; q++) acc[i][j][q] = 0;

    #pragma unroll
    for (int s = 0; s < NSTAGES - 1; s++) {
        load_chunk(s, s);
        asm volatile("cp.async.commit_group;" ::: "memory");
    }

    const uint32_t a_row   = wm * 64 + (lid & 15);
    const uint32_t a_kh    = (uint32_t)(lid >> 4) * 16;
    const uint32_t b_row   = wn * 64 + ((lid >> 4) & 1) * 8 + (lid & 7);
    const uint32_t b_kh    = (uint32_t)((lid >> 3) & 1) * 16;

    int stage = 0;
    for (int c = 0; c < NCHUNK; c++) {
        asm volatile("cp.async.wait_group %0;" :: "n"(1) : "memory");
        __syncthreads();

        const uint32_t abase = data_base + stage * STAGE_BYTES;
        const uint32_t bbase = abase + A_STAGE_BYTES;
        #pragma unroll
        for (int kk = 0; kk < 4; kk++) {        // 4 k32 steps per 128-byte chunk
            uint32_t a[4][4];
            #pragma unroll
            for (int mt = 0; mt < 4; mt++) {
                uint32_t off = (a_row + mt * 16) * 128 + kk * 32 + a_kh;
                ldmx4(a[mt], abase + sw(off));
            }
            #pragma unroll
            for (int nt = 0; nt < 4; nt++) {
                uint32_t b[4];
                uint32_t off = (b_row + nt * 16) * 128 + kk * 32 + b_kh;
                ldmx4(b, bbase + sw(off));
                #pragma unroll
                for (int mt = 0; mt < 4; mt++) {
                    mma16832(acc[mt][nt * 2 + 0], a[mt], b[0], b[1]);
                    mma16832(acc[mt][nt * 2 + 1], a[mt], b[2], b[3]);
                }
            }
        }
        if (c + NSTAGES - 1 < NCHUNK) load_chunk(c + NSTAGES - 1, (c + NSTAGES - 1) % NSTAGES);
        asm volatile("cp.async.commit_group;" ::: "memory");
        stage = (stage + 1 == NSTAGES) ? 0 : stage + 1;
    }

    // ---- epilogue: fine o-FWHT (bits 0..5) in exact int32, then scale ----
    #pragma unroll
    for (int mt = 0; mt < 4; mt++)
        #pragma unroll
        for (int j = 0; j < 8; j++) {
            int a0 = acc[mt][j][0], b0 = acc[mt][j][1];
            acc[mt][j][0] = a0 + b0; acc[mt][j][1] = a0 - b0;
            int a1 = acc[mt][j][2], b1 = acc[mt][j][3];
            acc[mt][j][2] = a1 + b1; acc[mt][j][3] = a1 - b1;
        }
    #pragma unroll
    for (int m = 1; m <= 2; m <<= 1) {
        const bool hi = (lid & m) != 0;
        #pragma unroll
        for (int mt = 0; mt < 4; mt++)
            #pragma unroll
            for (int j = 0; j < 8; j++)
                #pragma unroll
                for (int q = 0; q < 4; q++) {
                    int f = acc[mt][j][q];
                    int t = __shfl_xor_sync(0xFFFFFFFFu, f, m);
                    acc[mt][j][q] = hi ? (t - f) : (f + t);
                }
    }
    #pragma unroll
    for (int m = 1; m <= 4; m <<= 1)
        #pragma unroll
        for (int mt = 0; mt < 4; mt++)
            #pragma unroll
            for (int j = 0; j < 8; j++)
                if (!(j & m))
                    #pragma unroll
                    for (int q = 0; q < 4; q++) {
                        int a = acc[mt][j][q], b = acc[mt][j ^ m][q];
                        acc[mt][j][q] = a + b; acc[mt][j ^ m][q] = a - b;
                    }

    const float sc = g_wscale;
    const int r0 = tileM * TILE_M + wm * 64 + (lid >> 2);
    const int c0 = tileN * TILE_N + wn * 64 + 2 * (lid & 3);
    #pragma unroll
    for (int mt = 0; mt < 4; mt++) {
        float* p = out + (size_t)(r0 + mt * 16) * DIN + c0;
        #pragma unroll
        for (int j = 0; j < 8; j++) {
            *reinterpret_cast<float2*>(p + j * 8) =
                make_float2((float)acc[mt][j][0] * sc, (float)acc[mt][j][1] * sc);
            *reinterpret_cast<float2*>(p + j * 8 + (size_t)8 * DIN) =
                make_float2((float)acc[mt][j][2] * sc, (float)acc[mt][j][3] * sc);
        }
    }
}

// ---------- kernel 5: coarse o-FWHT (bits 6..11), in place on out ----------
__global__ void __launch_bounds__(256) out_coarse(float* __restrict__ out) {
    const int t = threadIdx.x;
    const int row = blockIdx.x * 4 + (t >> 6);
    const int lo = t & 63;
    float* p = out + (size_t)row * DIN + lo;
    float v[64];
    #pragma unroll
    for (int j = 0; j < 64; j++) v[j] = p[j * 64];
    #pragma unroll
    for (int b = 0; b < 6; b++) {
        const int m = 1 << b;
        #pragma unroll
        for (int k = 0; k < 64; k++) {
            if (!(k & m)) {
                float a = v[k], c = v[k ^ m];
                v[k] = a + c; v[k ^ m] = a - c;
            }
        }
    }
    #pragma unroll
    for (int j = 0; j < 64; j++) p[j * 64] = v[j];
}

// ---------- launch ----------
extern "C" void kernel_launch(void* const* d_in, const int* in_sizes, int n_in,
                              void* d_out, int out_size) {
    const float* x     = (const float*)d_in[0];
    const float* gamma = (const float*)d_in[1];
    const float* beta  = (const float*)d_in[2];
    const float* w     = (const float*)d_in[3];
    float* out = (float*)d_out;

    wabs_part<<<256, 256>>>(w);                    // launch 0
    w_fwht<<<ROWS_W, 256>>>(w);                    // launch 1
    ln_quant<<<ROWS_X, 256>>>(x, gamma, beta);     // launch 2
    cudaFuncSetAttribute(gemm_kernel, cudaFuncAttributeMaxDynamicSharedMemorySize, SMEM_GEMM);
    gemm_kernel<<<dim3(32, 64), 128, SMEM_GEMM>>>(out);   // launch 3 (ncu target)
    out_coarse<<<ROWS_X / 4, 256>>>(out);          // launch 4
}

// round 14
// speedup vs baseline: 2.9057x; 2.9057x over previous
#include <cuda_runtime.h>
#include <cuda_fp16.h>
#include <stdint.h>

#define DIN      4096
#define ROWS_X   8192
#define ROWS_W   4096
#define NSTAGES  3
#define NCHUNK   64
#define TILE_M   128
#define TILE_N   128
#define A_STAGE_BYTES (TILE_M*128)              // 16 KB
#define B_STAGE_BYTES (TILE_N*128)              // 16 KB
#define STAGE_BYTES   (A_STAGE_BYTES + B_STAGE_BYTES)
#define SMEM_GEMM     (NSTAGES*STAGE_BYTES + 1024)

__device__ __align__(16) __half g_Xq[(size_t)ROWS_X * DIN];   // 64 MB
__device__ __align__(16) __half g_Wh[(size_t)ROWS_W * DIN];   // 32 MB
__device__ float g_partials[256];
__device__ float g_wscale;

// ---------- helpers ----------
static __device__ __forceinline__ uint32_t smem_u32(const void* p) {
    uint32_t a;
    asm("{ .reg .u64 t; cvta.to.shared.u64 t, %1; cvt.u32.u64 %0, t; }" : "=r"(a) : "l"(p));
    return a;
}
static __device__ __forceinline__ void cp16(uint32_t dst, const void* src) {
    asm volatile("cp.async.cg.shared.global [%0], [%1], 16;" :: "r"(dst), "l"(src) : "memory");
}
static __device__ __forceinline__ void ldmx4(uint32_t* r, uint32_t addr) {
    asm volatile("ldmatrix.sync.aligned.m8n8.x4.shared.b16 {%0,%1,%2,%3}, [%4];"
                 : "=r"(r[0]), "=r"(r[1]), "=r"(r[2]), "=r"(r[3]) : "r"(addr));
}
static __device__ __forceinline__ void mma16816(float* d, const uint32_t* a,
                                                uint32_t b0, uint32_t b1) {
    asm volatile(
        "mma.sync.aligned.m16n8k16.row.col.f32.f16.f16.f32 "
        "{%0,%1,%2,%3}, {%4,%5,%6,%7}, {%8,%9}, {%0,%1,%2,%3};"
        : "+f"(d[0]), "+f"(d[1]), "+f"(d[2]), "+f"(d[3])
        : "r"(a[0]), "r"(a[1]), "r"(a[2]), "r"(a[3]), "r"(b0), "r"(b1));
}
static __device__ __forceinline__ uint32_t sw(uint32_t off) {
    return off ^ ((off >> 3) & 0x70);
}

// radix-16 in-register Hadamard butterfly (4 stages on disjoint bits)
static __device__ __forceinline__ void bfly16(float* v) {
    #pragma unroll
    for (int b = 0; b < 4; b++) {
        const int m = 1 << b;
        #pragma unroll
        for (int k = 0; k < 16; k++) {
            if (!(k & m)) {
                float a = v[k], c = v[k ^ m];
                v[k] = a + c; v[k ^ m] = a - c;
            }
        }
    }
}
static __device__ __forceinline__ int P16(int i) { return i + (i >> 4); }

// block-wide reduction over 512 threads (16 warps)
template <int OP>
static __device__ __forceinline__ float block_red(float v, float* red16, int tid) {
    #pragma unroll
    for (int o = 16; o > 0; o >>= 1) {
        float t = __shfl_xor_sync(0xFFFFFFFFu, v, o);
        v = (OP == 0) ? (v + t) : fmaxf(v, t);
    }
    if ((tid & 31) == 0) red16[tid >> 5] = v;
    __syncthreads();
    float r = red16[0];
    #pragma unroll
    for (int i = 1; i < 16; i++)
        r = (OP == 0) ? (r + red16[i]) : fmaxf(r, red16[i]);
    __syncthreads();
    return r;
}

// ---------- kernel 1: fused |w| partials (blocks 0..255) + LayerNorm-quantize ----------
__global__ void __launch_bounds__(512) prep1(const float* __restrict__ x,
                                             const float* __restrict__ gamma,
                                             const float* __restrict__ beta,
                                             const float* __restrict__ w) {
    __shared__ float red[512];
    const int tid = threadIdx.x;

    if (blockIdx.x < 256) {
        // ---- |w| partial sums ----
        const size_t s0 = (size_t)blockIdx.x * 65536;
        float s = 0.f;
        for (int i = tid; i < 65536; i += 512) s += fabsf(w[s0 + i]);
        red[tid] = s; __syncthreads();
        #pragma unroll
        for (int o = 256; o > 0; o >>= 1) {
            if (tid < o) red[tid] += red[tid + o];
            __syncthreads();
        }
        if (tid == 0) g_partials[blockIdx.x] = red[0];
        return;
    }

    // ---- LayerNorm + absmax quantize (coalesced), one row ----
    const int row = blockIdx.x - 256;
    const float* xr = x + (size_t)row * DIN;
    const int ca = tid * 4;
    const int cb = ca + 2048;

    float v[8];
    {
        float4 pa = *reinterpret_cast<const float4*>(xr + ca);
        float4 pb = *reinterpret_cast<const float4*>(xr + cb);
        v[0]=pa.x; v[1]=pa.y; v[2]=pa.z; v[3]=pa.w;
        v[4]=pb.x; v[5]=pb.y; v[6]=pb.z; v[7]=pb.w;
    }
    float s = 0.f;
    #pragma unroll
    for (int i = 0; i < 8; i++) s += v[i];
    const float mu = block_red<0>(s, red, tid) * (1.0f / DIN);

    float sq = 0.f;
    #pragma unroll
    for (int i = 0; i < 8; i++) { float d = v[i] - mu; sq += d * d; }
    const float rstd = 1.0f / sqrtf(block_red<0>(sq, red, tid) * (1.0f / DIN) + 1e-5f);

    float g[8], b[8];
    {
        float4 ga = *reinterpret_cast<const float4*>(gamma + ca);
        float4 gb = *reinterpret_cast<const float4*>(gamma + cb);
        float4 ba = *reinterpret_cast<const float4*>(beta + ca);
        float4 bb = *reinterpret_cast<const float4*>(beta + cb);
        g[0]=ga.x; g[1]=ga.y; g[2]=ga.z; g[3]=ga.w;
        g[4]=gb.x; g[5]=gb.y; g[6]=gb.z; g[7]=gb.w;
        b[0]=ba.x; b[1]=ba.y; b[2]=ba.z; b[3]=ba.w;
        b[4]=bb.x; b[5]=bb.y; b[6]=bb.z; b[7]=bb.w;
    }

    float y[8];
    float amax = 0.f;
    #pragma unroll
    for (int i = 0; i < 8; i++) {
        y[i] = (v[i] - mu) * rstd * g[i] + b[i];
        amax = fmaxf(amax, fabsf(y[i]));
    }
    const float scale = fminf(fmaxf(block_red<1>(amax, red, tid), 1e-6f), 1e6f);
    const float sf = fminf(fmaxf(7.0f / scale, 1e-6f), 1e6f);

    __half h[8];
    #pragma unroll
    for (int i = 0; i < 8; i++) {
        float q = fminf(fmaxf(rintf(y[i] * sf), -7.0f), 7.0f);
        h[i] = __float2half_rn(q);
    }
    __half* dst = g_Xq + (size_t)row * DIN;
    *reinterpret_cast<uint2*>(dst + ca) = *reinterpret_cast<uint2*>(h);
    *reinterpret_cast<uint2*>(dst + cb) = *reinterpret_cast<uint2*>(h + 4);
}

// final reduce of the 256 partials (deterministic tree).
static __device__ __forceinline__ float wscale_from_partials(float* red) {
    const int tid = threadIdx.x;
    if (tid < 256) red[tid] = g_partials[tid];
    __syncthreads();
    #pragma unroll
    for (int o = 128; o > 0; o >>= 1) {
        if (tid < o) red[tid] += red[tid + o];
        __syncthreads();
    }
    return red[0] * (1.0f / 16777216.0f);
}

// ---------- kernel 2: weight ternarize + radix-16 row FWHT (over d) -> fp16 ----------
__global__ void __launch_bounds__(256) w_fwht(const float* __restrict__ w) {
    __shared__ float s[4096 + 256];
    const int t = threadIdx.x;
    const float* wr = w + (size_t)blockIdx.x * DIN;
    const float wscale = wscale_from_partials(s);
    const float thr = 0.5f * wscale;
    if (blockIdx.x == 0 && t == 0) g_wscale = wscale;   // publish for gemm epilogue
    __syncthreads();

    float v[16];
    #pragma unroll
    for (int q = 0; q < 4; q++) {
        float4 p = *reinterpret_cast<const float4*>(wr + t * 16 + q * 4);
        v[q*4+0]=p.x; v[q*4+1]=p.y; v[q*4+2]=p.z; v[q*4+3]=p.w;
    }
    #pragma unroll
    for (int k = 0; k < 16; k++)
        v[k] = (v[k] > thr) ? 1.0f : ((v[k] < -thr) ? -1.0f : 0.0f);

    bfly16(v);                              // d bits 0-3
    #pragma unroll
    for (int k = 0; k < 16; k++) s[P16(t * 16 + k)] = v[k];
    __syncthreads();

    const int base = (t & 15) + (t >> 4) * 256;
    #pragma unroll
    for (int k = 0; k < 16; k++) v[k] = s[P16(base + 16 * k)];
    bfly16(v);                              // d bits 4-7
    #pragma unroll
    for (int k = 0; k < 16; k++) s[P16(base + 16 * k)] = v[k];
    __syncthreads();

    #pragma unroll
    for (int k = 0; k < 16; k++) v[k] = s[P16(t + 256 * k)];
    bfly16(v);                              // d bits 8-11
    __half* dst = g_Wh + (size_t)blockIdx.x * DIN;
    #pragma unroll
    for (int k = 0; k < 16; k++) dst[t + 256 * k] = __float2half_rn(v[k]);
}

// ---------- kernel 3: coarse column FWHT_64 over o-bits 6..11, in place on g_Wh ----
__global__ void __launch_bounds__(128) w_colfwht() {
    const int t   = threadIdx.x;
    const int cg  = blockIdx.x;     // 0..31: 128-col group
    const int olo = blockIdx.y;     // 0..63
    __half* base = g_Wh + (size_t)olo * DIN + cg * 128 + t;
    float v[64];
    #pragma unroll
    for (int k = 0; k < 64; k++)
        v[k] = __half2float(base[(size_t)k * 64 * DIN]);
    #pragma unroll
    for (int b = 0; b < 6; b++) {
        const int m = 1 << b;
        #pragma unroll
        for (int k = 0; k < 64; k++) {
            if (!(k & m)) {
                float a = v[k], c = v[k ^ m];
                v[k] = a + c; v[k ^ m] = a - c;
            }
        }
    }
    #pragma unroll
    for (int k = 0; k < 64; k++)
        base[(size_t)k * 64 * DIN] = __float2half_rn(v[k]);
}

// ---------- kernel 4: HMMA GEMM + fine FWHT_64 epilogue + scale ----------
__global__ void __launch_bounds__(128, 2) gemm_kernel(float* __restrict__ out) {
    extern __shared__ char smem_raw[];
    const uint32_t data_base = (smem_u32(smem_raw) + 1023u) & ~1023u;
    const int tid = threadIdx.x;
    const int wid = tid >> 5;
    const int lid = tid & 31;
    const int wm = wid >> 1;        // 0..1 (64-row slab)
    const int wn = wid & 1;         // 0..1 (64-col slab)
    const int tileN = blockIdx.x;   // 0..31
    const int tileM = blockIdx.y;   // 0..63

    const char* Ag = (const char*)(g_Xq + (size_t)tileM * TILE_M * DIN);
    const char* Bg = (const char*)(g_Wh + (size_t)tileN * TILE_N * DIN);

    auto load_chunk = [&](int c, int stage) {
        const uint32_t abase = data_base + stage * STAGE_BYTES;
        const uint32_t bbase = abase + A_STAGE_BYTES;
        #pragma unroll
        for (int t = 0; t < 8; t++) {
            int idx = tid + t * 128;
            int r = idx >> 3, j = idx & 7;
            uint32_t off = (uint32_t)(r * 128 + j * 16);
            cp16(abase + sw(off), Ag + (size_t)r * (DIN * 2) + c * 128 + j * 16);
        }
        #pragma unroll
        for (int t = 0; t < 8; t++) {
            int idx = tid + t * 128;
            int r = idx >> 3, j = idx & 7;
            uint32_t off = (uint32_t)(r * 128 + j * 16);
            cp16(bbase + sw(off), Bg + (size_t)r * (DIN * 2) + c * 128 + j * 16);
        }
    };

    float acc[4][8][4];
    #pragma unroll
    for (int i = 0; i < 4; i++)
        #pragma unroll
        for (int j = 0; j < 8; j++)
            #pragma unroll
            for (int q = 0; q < 4; q++) acc[i][j][q] = 0.f;

    #pragma unroll
    for (int s = 0; s < NSTAGES - 1; s++) {
        load_chunk(s, s);
        asm volatile("cp.async.commit_group;" ::: "memory");
    }

    const uint32_t a_row   = wm * 64 + (lid & 15);
    const uint32_t a_kh    = (uint32_t)(lid >> 4) * 16;
    const uint32_t b_row   = wn * 64 + ((lid >> 4) & 1) * 8 + (lid & 7);
    const uint32_t b_kh    = (uint32_t)((lid >> 3) & 1) * 16;

    int stage = 0;
    for (int c = 0; c < NCHUNK; c++) {
        asm volatile("cp.async.wait_group %0;" :: "n"(1) : "memory");
        __syncthreads();

        // load-at-top: stage (c+2)%3 == (c-1)%3, fully read last iteration;
        // the sync above published that. Loads get a full iteration of latency.
        if (c + NSTAGES - 1 < NCHUNK) load_chunk(c + NSTAGES - 1, (c + NSTAGES - 1) % NSTAGES);
        asm volatile("cp.async.commit_group;" ::: "memory");

        const uint32_t abase = data_base + stage * STAGE_BYTES;
        const uint32_t bbase = abase + A_STAGE_BYTES;
        #pragma unroll
        for (int kk = 0; kk < 4; kk++) {
            uint32_t a[4][4];
            #pragma unroll
            for (int mt = 0; mt < 4; mt++) {
                uint32_t off = (a_row + mt * 16) * 128 + kk * 32 + a_kh;
                ldmx4(a[mt], abase + sw(off));
            }
            #pragma unroll
            for (int nt = 0; nt < 4; nt++) {
                uint32_t b[4];
                uint32_t off = (b_row + nt * 16) * 128 + kk * 32 + b_kh;
                ldmx4(b, bbase + sw(off));
                #pragma unroll
                for (int mt = 0; mt < 4; mt++) {
                    mma16816(acc[mt][nt * 2 + 0], a[mt], b[0], b[1]);
                    mma16816(acc[mt][nt * 2 + 1], a[mt], b[2], b[3]);
                }
            }
        }
        stage = (stage + 1 == NSTAGES) ? 0 : stage + 1;
    }

    // ---- epilogue: fine FWHT_64 over columns (o-bits 0..5) within this warp ----
    #pragma unroll
    for (int mt = 0; mt < 4; mt++)
        #pragma unroll
        for (int j = 0; j < 8; j++) {
            float a0 = acc[mt][j][0], b0 = acc[mt][j][1];
            acc[mt][j][0] = a0 + b0; acc[mt][j][1] = a0 - b0;
            float a1 = acc[mt][j][2], b1 = acc[mt][j][3];
            acc[mt][j][2] = a1 + b1; acc[mt][j][3] = a1 - b1;
        }
    #pragma unroll
    for (int m = 1; m <= 2; m <<= 1) {
        const bool hi = (lid & m) != 0;
        #pragma unroll
        for (int mt = 0; mt < 4; mt++)
            #pragma unroll
            for (int j = 0; j < 8; j++)
                #pragma unroll
                for (int q = 0; q < 4; q++) {
                    float f = acc[mt][j][q];
                    float t = __shfl_xor_sync(0xFFFFFFFFu, f, m);
                    acc[mt][j][q] = hi ? (t - f) : (f + t);
                }
    }
    #pragma unroll
    for (int m = 1; m <= 4; m <<= 1)
        #pragma unroll
        for (int mt = 0; mt < 4; mt++)
            #pragma unroll
            for (int j = 0; j < 8; j++)
                if (!(j & m))
                    #pragma unroll
                    for (int q = 0; q < 4; q++) {
                        float a = acc[mt][j][q], b = acc[mt][j ^ m][q];
                        acc[mt][j][q] = a + b; acc[mt][j ^ m][q] = a - b;
                    }

    const float sc = g_wscale;
    const int r0 = tileM * TILE_M + wm * 64 + (lid >> 2);
    const int c0 = tileN * TILE_N + wn * 64 + 2 * (lid & 3);
    #pragma unroll
    for (int mt = 0; mt < 4; mt++) {
        float* p = out + (size_t)(r0 + mt * 16) * DIN + c0;
        #pragma unroll
        for (int j = 0; j < 8; j++) {
            *reinterpret_cast<float2*>(p + j * 8) =
                make_float2(acc[mt][j][0] * sc, acc[mt][j][1] * sc);
            *reinterpret_cast<float2*>(p + j * 8 + (size_t)8 * DIN) =
                make_float2(acc[mt][j][2] * sc, acc[mt][j][3] * sc);
        }
    }
}

// ---------- launch ----------
extern "C" void kernel_launch(void* const* d_in, const int* in_sizes, int n_in,
                              void* d_out, int out_size) {
    const float* x     = (const float*)d_in[0];
    const float* gamma = (const float*)d_in[1];
    const float* beta  = (const float*)d_in[2];
    const float* w     = (const float*)d_in[3];
    float* out = (float*)d_out;

    prep1<<<256 + ROWS_X, 512>>>(x, gamma, beta, w);      // launch 0
    w_fwht<<<ROWS_W, 256>>>(w);                           // launch 1
    w_colfwht<<<dim3(32, 64), 128>>>();                   // launch 2
    cudaFuncSetAttribute(gemm_kernel, cudaFuncAttributeMaxDynamicSharedMemorySize, SMEM_GEMM);
    gemm_kernel<<<dim3(32, 64), 128, SMEM_GEMM>>>(out);   // launch 3 (ncu target)
}

// round 15
// speedup vs baseline: 2.9195x; 1.0047x over previous
#include <cuda_runtime.h>
#include <cuda_fp16.h>
#include <stdint.h>

#define DIN      4096
#define ROWS_X   8192
#define ROWS_W   4096
#define NSTAGES  3
#define NCHUNK   64
#define TILE_M   128
#define TILE_N   128
#define A_STAGE_BYTES (TILE_M*128)              // 16 KB
#define B_STAGE_BYTES (TILE_N*128)              // 16 KB
#define STAGE_BYTES   (A_STAGE_BYTES + B_STAGE_BYTES)
#define SMEM_GEMM     (NSTAGES*STAGE_BYTES + 1024)

__device__ __align__(16) __half g_Xq[(size_t)ROWS_X * DIN];   // 64 MB
__device__ __align__(16) __half g_Wh[(size_t)ROWS_W * DIN];   // 32 MB
__device__ float g_partials[256];
__device__ float g_wscale;

// ---------- helpers ----------
static __device__ __forceinline__ uint32_t smem_u32(const void* p) {
    uint32_t a;
    asm("{ .reg .u64 t; cvta.to.shared.u64 t, %1; cvt.u32.u64 %0, t; }" : "=r"(a) : "l"(p));
    return a;
}
static __device__ __forceinline__ void cp16(uint32_t dst, const void* src) {
    asm volatile("cp.async.cg.shared.global [%0], [%1], 16;" :: "r"(dst), "l"(src) : "memory");
}
static __device__ __forceinline__ void ldmx4(uint32_t* r, uint32_t addr) {
    asm volatile("ldmatrix.sync.aligned.m8n8.x4.shared.b16 {%0,%1,%2,%3}, [%4];"
                 : "=r"(r[0]), "=r"(r[1]), "=r"(r[2]), "=r"(r[3]) : "r"(addr));
}
static __device__ __forceinline__ void mma16816(float* d, const uint32_t* a,
                                                uint32_t b0, uint32_t b1) {
    asm volatile(
        "mma.sync.aligned.m16n8k16.row.col.f32.f16.f16.f32 "
        "{%0,%1,%2,%3}, {%4,%5,%6,%7}, {%8,%9}, {%0,%1,%2,%3};"
        : "+f"(d[0]), "+f"(d[1]), "+f"(d[2]), "+f"(d[3])
        : "r"(a[0]), "r"(a[1]), "r"(a[2]), "r"(a[3]), "r"(b0), "r"(b1));
}
static __device__ __forceinline__ uint32_t sw(uint32_t off) {
    return off ^ ((off >> 3) & 0x70);
}

// radix-16 in-register Hadamard butterfly (4 stages on disjoint bits)
static __device__ __forceinline__ void bfly16(float* v) {
    #pragma unroll
    for (int b = 0; b < 4; b++) {
        const int m = 1 << b;
        #pragma unroll
        for (int k = 0; k < 16; k++) {
            if (!(k & m)) {
                float a = v[k], c = v[k ^ m];
                v[k] = a + c; v[k ^ m] = a - c;
            }
        }
    }
}
static __device__ __forceinline__ int P16(int i) { return i + (i >> 4); }

// block-wide reduction over 512 threads (16 warps)
template <int OP>
static __device__ __forceinline__ float block_red(float v, float* red16, int tid) {
    #pragma unroll
    for (int o = 16; o > 0; o >>= 1) {
        float t = __shfl_xor_sync(0xFFFFFFFFu, v, o);
        v = (OP == 0) ? (v + t) : fmaxf(v, t);
    }
    if ((tid & 31) == 0) red16[tid >> 5] = v;
    __syncthreads();
    float r = red16[0];
    #pragma unroll
    for (int i = 1; i < 16; i++)
        r = (OP == 0) ? (r + red16[i]) : fmaxf(r, red16[i]);
    __syncthreads();
    return r;
}

// ---------- kernel 1: fused |w| partials (blocks 0..255) + LayerNorm-quantize ----------
__global__ void __launch_bounds__(512) prep1(const float* __restrict__ x,
                                             const float* __restrict__ gamma,
                                             const float* __restrict__ beta,
                                             const float* __restrict__ w) {
    __shared__ float red[512];
    const int tid = threadIdx.x;

    if (blockIdx.x < 256) {
        // ---- |w| partial sums ----
        const size_t s0 = (size_t)blockIdx.x * 65536;
        float s = 0.f;
        for (int i = tid; i < 65536; i += 512) s += fabsf(w[s0 + i]);
        red[tid] = s; __syncthreads();
        #pragma unroll
        for (int o = 256; o > 0; o >>= 1) {
            if (tid < o) red[tid] += red[tid + o];
            __syncthreads();
        }
        if (tid == 0) g_partials[blockIdx.x] = red[0];
        return;
    }

    // ---- LayerNorm + absmax quantize (coalesced), one row ----
    const int row = blockIdx.x - 256;
    const float* xr = x + (size_t)row * DIN;
    const int ca = tid * 4;
    const int cb = ca + 2048;

    float v[8];
    {
        float4 pa = *reinterpret_cast<const float4*>(xr + ca);
        float4 pb = *reinterpret_cast<const float4*>(xr + cb);
        v[0]=pa.x; v[1]=pa.y; v[2]=pa.z; v[3]=pa.w;
        v[4]=pb.x; v[5]=pb.y; v[6]=pb.z; v[7]=pb.w;
    }
    float s = 0.f;
    #pragma unroll
    for (int i = 0; i < 8; i++) s += v[i];
    const float mu = block_red<0>(s, red, tid) * (1.0f / DIN);

    float sq = 0.f;
    #pragma unroll
    for (int i = 0; i < 8; i++) { float d = v[i] - mu; sq += d * d; }
    const float rstd = 1.0f / sqrtf(block_red<0>(sq, red, tid) * (1.0f / DIN) + 1e-5f);

    float g[8], b[8];
    {
        float4 ga = *reinterpret_cast<const float4*>(gamma + ca);
        float4 gb = *reinterpret_cast<const float4*>(gamma + cb);
        float4 ba = *reinterpret_cast<const float4*>(beta + ca);
        float4 bb = *reinterpret_cast<const float4*>(beta + cb);
        g[0]=ga.x; g[1]=ga.y; g[2]=ga.z; g[3]=ga.w;
        g[4]=gb.x; g[5]=gb.y; g[6]=gb.z; g[7]=gb.w;
        b[0]=ba.x; b[1]=ba.y; b[2]=ba.z; b[3]=ba.w;
        b[4]=bb.x; b[5]=bb.y; b[6]=bb.z; b[7]=bb.w;
    }

    float y[8];
    float amax = 0.f;
    #pragma unroll
    for (int i = 0; i < 8; i++) {
        y[i] = (v[i] - mu) * rstd * g[i] + b[i];
        amax = fmaxf(amax, fabsf(y[i]));
    }
    const float scale = fminf(fmaxf(block_red<1>(amax, red, tid), 1e-6f), 1e6f);
    const float sf = fminf(fmaxf(7.0f / scale, 1e-6f), 1e6f);

    __half h[8];
    #pragma unroll
    for (int i = 0; i < 8; i++) {
        float q = fminf(fmaxf(rintf(y[i] * sf), -7.0f), 7.0f);
        h[i] = __float2half_rn(q);
    }
    __half* dst = g_Xq + (size_t)row * DIN;
    *reinterpret_cast<uint2*>(dst + ca) = *reinterpret_cast<uint2*>(h);
    *reinterpret_cast<uint2*>(dst + cb) = *reinterpret_cast<uint2*>(h + 4);
}

// final reduce of the 256 partials (deterministic tree).
static __device__ __forceinline__ float wscale_from_partials(float* red) {
    const int tid = threadIdx.x;
    if (tid < 256) red[tid] = g_partials[tid];
    __syncthreads();
    #pragma unroll
    for (int o = 128; o > 0; o >>= 1) {
        if (tid < o) red[tid] += red[tid + o];
        __syncthreads();
    }
    return red[0] * (1.0f / 16777216.0f);
}

// ---------- kernel 2: weight ternarize + radix-16 row FWHT (over d) -> fp16 ----------
__global__ void __launch_bounds__(256) w_fwht(const float* __restrict__ w) {
    __shared__ float s[4096 + 256];
    const int t = threadIdx.x;
    const float* wr = w + (size_t)blockIdx.x * DIN;
    const float wscale = wscale_from_partials(s);
    const float thr = 0.5f * wscale;
    if (blockIdx.x == 0 && t == 0) g_wscale = wscale;   // publish for gemm epilogue
    __syncthreads();

    float v[16];
    #pragma unroll
    for (int q = 0; q < 4; q++) {
        float4 p = *reinterpret_cast<const float4*>(wr + t * 16 + q * 4);
        v[q*4+0]=p.x; v[q*4+1]=p.y; v[q*4+2]=p.z; v[q*4+3]=p.w;
    }
    #pragma unroll
    for (int k = 0; k < 16; k++)
        v[k] = (v[k] > thr) ? 1.0f : ((v[k] < -thr) ? -1.0f : 0.0f);

    bfly16(v);                              // d bits 0-3
    #pragma unroll
    for (int k = 0; k < 16; k++) s[P16(t * 16 + k)] = v[k];
    __syncthreads();

    const int base = (t & 15) + (t >> 4) * 256;
    #pragma unroll
    for (int k = 0; k < 16; k++) v[k] = s[P16(base + 16 * k)];
    bfly16(v);                              // d bits 4-7
    #pragma unroll
    for (int k = 0; k < 16; k++) s[P16(base + 16 * k)] = v[k];
    __syncthreads();

    #pragma unroll
    for (int k = 0; k < 16; k++) v[k] = s[P16(t + 256 * k)];
    bfly16(v);                              // d bits 8-11
    __half* dst = g_Wh + (size_t)blockIdx.x * DIN;
    #pragma unroll
    for (int k = 0; k < 16; k++) dst[t + 256 * k] = __float2half_rn(v[k]);
}

// ---------- kernel 3: coarse column FWHT_64 over o-bits 6..11, in place on g_Wh ----
__global__ void __launch_bounds__(128) w_colfwht() {
    const int t   = threadIdx.x;
    const int cg  = blockIdx.x;     // 0..31: 128-col group
    const int olo = blockIdx.y;     // 0..63
    __half* base = g_Wh + (size_t)olo * DIN + cg * 128 + t;
    float v[64];
    #pragma unroll
    for (int k = 0; k < 64; k++)
        v[k] = __half2float(base[(size_t)k * 64 * DIN]);
    #pragma unroll
    for (int b = 0; b < 6; b++) {
        const int m = 1 << b;
        #pragma unroll
        for (int k = 0; k < 64; k++) {
            if (!(k & m)) {
                float a = v[k], c = v[k ^ m];
                v[k] = a + c; v[k ^ m] = a - c;
            }
        }
    }
    #pragma unroll
    for (int k = 0; k < 64; k++)
        base[(size_t)k * 64 * DIN] = __float2half_rn(v[k]);
}

// ---------- kernel 4: HMMA GEMM + fine FWHT_64 epilogue + scale ----------
__global__ void __launch_bounds__(128, 2) gemm_kernel(float* __restrict__ out) {
    extern __shared__ char smem_raw[];
    const uint32_t data_base = (smem_u32(smem_raw) + 1023u) & ~1023u;
    const int tid = threadIdx.x;
    const int wid = tid >> 5;
    const int lid = tid & 31;
    const int wm = wid >> 1;        // 0..1 (64-row slab)
    const int wn = wid & 1;         // 0..1 (64-col slab)
    const int tileN = blockIdx.x;   // 0..31
    const int tileM = blockIdx.y;   // 0..63

    const char* Ag = (const char*)(g_Xq + (size_t)tileM * TILE_M * DIN);
    const char* Bg = (const char*)(g_Wh + (size_t)tileN * TILE_N * DIN);

    auto load_chunk = [&](int c, int stage) {
        const uint32_t abase = data_base + stage * STAGE_BYTES;
        const uint32_t bbase = abase + A_STAGE_BYTES;
        #pragma unroll
        for (int t = 0; t < 8; t++) {
            int idx = tid + t * 128;
            int r = idx >> 3, j = idx & 7;
            uint32_t off = (uint32_t)(r * 128 + j * 16);
            cp16(abase + sw(off), Ag + (size_t)r * (DIN * 2) + c * 128 + j * 16);
        }
        #pragma unroll
        for (int t = 0; t < 8; t++) {
            int idx = tid + t * 128;
            int r = idx >> 3, j = idx & 7;
            uint32_t off = (uint32_t)(r * 128 + j * 16);
            cp16(bbase + sw(off), Bg + (size_t)r * (DIN * 2) + c * 128 + j * 16);
        }
    };

    float acc[4][8][4];
    #pragma unroll
    for (int i = 0; i < 4; i++)
        #pragma unroll
        for (int j = 0; j < 8; j++)
            #pragma unroll
            for (int q = 0; q < 4; q++) acc[i][j][q] = 0.f;

    #pragma unroll
    for (int s = 0; s < NSTAGES - 1; s++) {
        load_chunk(s, s);
        asm volatile("cp.async.commit_group;" ::: "memory");
    }

    const uint32_t a_row   = wm * 64 + (lid & 15);
    const uint32_t a_kh    = (uint32_t)(lid >> 4) * 16;
    const uint32_t b_row   = wn * 64 + ((lid >> 4) & 1) * 8 + (lid & 7);
    const uint32_t b_kh    = (uint32_t)((lid >> 3) & 1) * 16;

    int stage = 0;
    for (int c = 0; c < NCHUNK; c++) {
        asm volatile("cp.async.wait_group %0;" :: "n"(1) : "memory");
        __syncthreads();

        const uint32_t abase = data_base + stage * STAGE_BYTES;
        const uint32_t bbase = abase + A_STAGE_BYTES;
        #pragma unroll
        for (int kk = 0; kk < 4; kk++) {
            uint32_t a[4][4];
            #pragma unroll
            for (int mt = 0; mt < 4; mt++) {
                uint32_t off = (a_row + mt * 16) * 128 + kk * 32 + a_kh;
                ldmx4(a[mt], abase + sw(off));
            }
            #pragma unroll
            for (int nt = 0; nt < 4; nt++) {
                uint32_t b[4];
                uint32_t off = (b_row + nt * 16) * 128 + kk * 32 + b_kh;
                ldmx4(b, bbase + sw(off));
                #pragma unroll
                for (int mt = 0; mt < 4; mt++) {
                    mma16816(acc[mt][nt * 2 + 0], a[mt], b[0], b[1]);
                    mma16816(acc[mt][nt * 2 + 1], a[mt], b[2], b[3]);
                }
            }
        }
        // load-after-compute: stage (c+2)%3 == (c-1)%3, fully read last iter, sync above
        if (c + NSTAGES - 1 < NCHUNK) load_chunk(c + NSTAGES - 1, (c + NSTAGES - 1) % NSTAGES);
        asm volatile("cp.async.commit_group;" ::: "memory");
        stage = (stage + 1 == NSTAGES) ? 0 : stage + 1;
    }

    // ---- epilogue: fine FWHT_64 over columns (o-bits 0..5) within this warp ----
    #pragma unroll
    for (int mt = 0; mt < 4; mt++)
        #pragma unroll
        for (int j = 0; j < 8; j++) {
            float a0 = acc[mt][j][0], b0 = acc[mt][j][1];
            acc[mt][j][0] = a0 + b0; acc[mt][j][1] = a0 - b0;
            float a1 = acc[mt][j][2], b1 = acc[mt][j][3];
            acc[mt][j][2] = a1 + b1; acc[mt][j][3] = a1 - b1;
        }
    #pragma unroll
    for (int m = 1; m <= 2; m <<= 1) {
        const bool hi = (lid & m) != 0;
        #pragma unroll
        for (int mt = 0; mt < 4; mt++)
            #pragma unroll
            for (int j = 0; j < 8; j++)
                #pragma unroll
                for (int q = 0; q < 4; q++) {
                    float f = acc[mt][j][q];
                    float t = __shfl_xor_sync(0xFFFFFFFFu, f, m);
                    acc[mt][j][q] = hi ? (t - f) : (f + t);
                }
    }
    #pragma unroll
    for (int m = 1; m <= 4; m <<= 1)
        #pragma unroll
        for (int mt = 0; mt < 4; mt++)
            #pragma unroll
            for (int j = 0; j < 8; j++)
                if (!(j & m))
                    #pragma unroll
                    for (int q = 0; q < 4; q++) {
                        float a = acc[mt][j][q], b = acc[mt][j ^ m][q];
                        acc[mt][j][q] = a + b; acc[mt][j ^ m][q] = a - b;
                    }

    const float sc = g_wscale;
    const int r0 = tileM * TILE_M + wm * 64 + (lid >> 2);
    const int c0 = tileN * TILE_N + wn * 64 + 2 * (lid & 3);
    #pragma unroll
    for (int mt = 0; mt < 4; mt++) {
        float* p = out + (size_t)(r0 + mt * 16) * DIN + c0;
        #pragma unroll
        for (int j = 0; j < 8; j++) {
            *reinterpret_cast<float2*>(p + j * 8) =
                make_float2(acc[mt][j][0] * sc, acc[mt][j][1] * sc);
            *reinterpret_cast<float2*>(p + j * 8 + (size_t)8 * DIN) =
                make_float2(acc[mt][j][2] * sc, acc[mt][j][3] * sc);
        }
    }
}

// ---------- launch ----------
extern "C" void kernel_launch(void* const* d_in, const int* in_sizes, int n_in,
                              void* d_out, int out_size) {
    const float* x     = (const float*)d_in[0];
    const float* gamma = (const float*)d_in[1];
    const float* beta  = (const float*)d_in[2];
    const float* w     = (const float*)d_in[3];
    float* out = (float*)d_out;

    prep1<<<256 + ROWS_X, 512>>>(x, gamma, beta, w);      // launch 0
    w_fwht<<<ROWS_W, 256>>>(w);                           // launch 1
    w_colfwht<<<dim3(32, 64), 128>>>();                   // launch 2
    cudaFuncSetAttribute(gemm_kernel, cudaFuncAttributeMaxDynamicSharedMemorySize, SMEM_GEMM);
    gemm_kernel<<<dim3(32, 64), 128, SMEM_GEMM>>>(out);   // launch 3 (ncu target)
}

// round 16
// speedup vs baseline: 2.9481x; 1.0098x over previous
#include <cuda_runtime.h>
#include <cuda_fp16.h>
#include <stdint.h>

#define DIN      4096
#define ROWS_X   8192
#define ROWS_W   4096
#define NSTAGES  3
#define NCHUNK   64
#define TILE_M   128
#define TILE_N   128
#define A_STAGE_BYTES (TILE_M*128)              // 16 KB
#define B_STAGE_BYTES (TILE_N*128)              // 16 KB
#define STAGE_BYTES   (A_STAGE_BYTES + B_STAGE_BYTES)
#define SMEM_GEMM     (NSTAGES*STAGE_BYTES + 1024)

__device__ __align__(16) __half g_Xq[(size_t)ROWS_X * DIN];   // 64 MB
__device__ __align__(16) __half g_Wh[(size_t)ROWS_W * DIN];   // 32 MB
__device__ float g_partials[256];
__device__ float g_wscale;

// ---------- helpers ----------
static __device__ __forceinline__ uint32_t smem_u32(const void* p) {
    uint32_t a;
    asm("{ .reg .u64 t; cvta.to.shared.u64 t, %1; cvt.u32.u64 %0, t; }" : "=r"(a) : "l"(p));
    return a;
}
static __device__ __forceinline__ void cp16(uint32_t dst, const void* src) {
    asm volatile("cp.async.cg.shared.global [%0], [%1], 16;" :: "r"(dst), "l"(src) : "memory");
}
static __device__ __forceinline__ void ldmx4(uint32_t* r, uint32_t addr) {
    asm volatile("ldmatrix.sync.aligned.m8n8.x4.shared.b16 {%0,%1,%2,%3}, [%4];"
                 : "=r"(r[0]), "=r"(r[1]), "=r"(r[2]), "=r"(r[3]) : "r"(addr));
}
static __device__ __forceinline__ void mma16816(float* d, const uint32_t* a,
                                                uint32_t b0, uint32_t b1) {
    asm volatile(
        "mma.sync.aligned.m16n8k16.row.col.f32.f16.f16.f32 "
        "{%0,%1,%2,%3}, {%4,%5,%6,%7}, {%8,%9}, {%0,%1,%2,%3};"
        : "+f"(d[0]), "+f"(d[1]), "+f"(d[2]), "+f"(d[3])
        : "r"(a[0]), "r"(a[1]), "r"(a[2]), "r"(a[3]), "r"(b0), "r"(b1));
}
static __device__ __forceinline__ uint32_t sw(uint32_t off) {
    return off ^ ((off >> 3) & 0x70);
}

// radix-16 in-register Hadamard butterfly (4 stages on disjoint bits)
static __device__ __forceinline__ void bfly16(float* v) {
    #pragma unroll
    for (int b = 0; b < 4; b++) {
        const int m = 1 << b;
        #pragma unroll
        for (int k = 0; k < 16; k++) {
            if (!(k & m)) {
                float a = v[k], c = v[k ^ m];
                v[k] = a + c; v[k ^ m] = a - c;
            }
        }
    }
}
static __device__ __forceinline__ int P16(int i) { return i + (i >> 4); }

// block-wide reduction over 512 threads (16 warps)
template <int OP>
static __device__ __forceinline__ float block_red(float v, float* red16, int tid) {
    #pragma unroll
    for (int o = 16; o > 0; o >>= 1) {
        float t = __shfl_xor_sync(0xFFFFFFFFu, v, o);
        v = (OP == 0) ? (v + t) : fmaxf(v, t);
    }
    if ((tid & 31) == 0) red16[tid >> 5] = v;
    __syncthreads();
    float r = red16[0];
    #pragma unroll
    for (int i = 1; i < 16; i++)
        r = (OP == 0) ? (r + red16[i]) : fmaxf(r, red16[i]);
    __syncthreads();
    return r;
}

// ---------- kernel 1: fused |w| partials (blocks 0..255) + LayerNorm-quantize ----------
__global__ void __launch_bounds__(512) prep1(const float* __restrict__ x,
                                             const float* __restrict__ gamma,
                                             const float* __restrict__ beta,
                                             const float* __restrict__ w) {
    __shared__ float red[512];
    const int tid = threadIdx.x;

    if (blockIdx.x < 256) {
        const size_t s0 = (size_t)blockIdx.x * 65536;
        float s = 0.f;
        for (int i = tid; i < 65536; i += 512) s += fabsf(w[s0 + i]);
        red[tid] = s; __syncthreads();
        #pragma unroll
        for (int o = 256; o > 0; o >>= 1) {
            if (tid < o) red[tid] += red[tid + o];
            __syncthreads();
        }
        if (tid == 0) g_partials[blockIdx.x] = red[0];
        return;
    }

    const int row = blockIdx.x - 256;
    const float* xr = x + (size_t)row * DIN;
    const int ca = tid * 4;
    const int cb = ca + 2048;

    float v[8];
    {
        float4 pa = *reinterpret_cast<const float4*>(xr + ca);
        float4 pb = *reinterpret_cast<const float4*>(xr + cb);
        v[0]=pa.x; v[1]=pa.y; v[2]=pa.z; v[3]=pa.w;
        v[4]=pb.x; v[5]=pb.y; v[6]=pb.z; v[7]=pb.w;
    }
    float s = 0.f;
    #pragma unroll
    for (int i = 0; i < 8; i++) s += v[i];
    const float mu = block_red<0>(s, red, tid) * (1.0f / DIN);

    float sq = 0.f;
    #pragma unroll
    for (int i = 0; i < 8; i++) { float d = v[i] - mu; sq += d * d; }
    const float rstd = 1.0f / sqrtf(block_red<0>(sq, red, tid) * (1.0f / DIN) + 1e-5f);

    float g[8], b[8];
    {
        float4 ga = *reinterpret_cast<const float4*>(gamma + ca);
        float4 gb = *reinterpret_cast<const float4*>(gamma + cb);
        float4 ba = *reinterpret_cast<const float4*>(beta + ca);
        float4 bb = *reinterpret_cast<const float4*>(beta + cb);
        g[0]=ga.x; g[1]=ga.y; g[2]=ga.z; g[3]=ga.w;
        g[4]=gb.x; g[5]=gb.y; g[6]=gb.z; g[7]=gb.w;
        b[0]=ba.x; b[1]=ba.y; b[2]=ba.z; b[3]=ba.w;
        b[4]=bb.x; b[5]=bb.y; b[6]=bb.z; b[7]=bb.w;
    }

    float y[8];
    float amax = 0.f;
    #pragma unroll
    for (int i = 0; i < 8; i++) {
        y[i] = (v[i] - mu) * rstd * g[i] + b[i];
        amax = fmaxf(amax, fabsf(y[i]));
    }
    const float scale = fminf(fmaxf(block_red<1>(amax, red, tid), 1e-6f), 1e6f);
    const float sf = fminf(fmaxf(7.0f / scale, 1e-6f), 1e6f);

    __half h[8];
    #pragma unroll
    for (int i = 0; i < 8; i++) {
        float q = fminf(fmaxf(rintf(y[i] * sf), -7.0f), 7.0f);
        h[i] = __float2half_rn(q);
    }
    __half* dst = g_Xq + (size_t)row * DIN;
    *reinterpret_cast<uint2*>(dst + ca) = *reinterpret_cast<uint2*>(h);
    *reinterpret_cast<uint2*>(dst + cb) = *reinterpret_cast<uint2*>(h + 4);
}

// final reduce of the 256 partials (deterministic tree).
static __device__ __forceinline__ float wscale_from_partials(float* red) {
    const int tid = threadIdx.x;
    if (tid < 256) red[tid] = g_partials[tid];
    __syncthreads();
    #pragma unroll
    for (int o = 128; o > 0; o >>= 1) {
        if (tid < o) red[tid] += red[tid + o];
        __syncthreads();
    }
    return red[0] * (1.0f / 16777216.0f);
}

// ---------- kernel 2: weight ternarize + radix-16 row FWHT (over d) -> fp16 ----------
__global__ void __launch_bounds__(256) w_fwht(const float* __restrict__ w) {
    __shared__ float s[4096 + 256];
    const int t = threadIdx.x;
    const float* wr = w + (size_t)blockIdx.x * DIN;
    const float wscale = wscale_from_partials(s);
    const float thr = 0.5f * wscale;
    if (blockIdx.x == 0 && t == 0) g_wscale = wscale;
    __syncthreads();

    float v[16];
    #pragma unroll
    for (int q = 0; q < 4; q++) {
        float4 p = *reinterpret_cast<const float4*>(wr + t * 16 + q * 4);
        v[q*4+0]=p.x; v[q*4+1]=p.y; v[q*4+2]=p.z; v[q*4+3]=p.w;
    }
    #pragma unroll
    for (int k = 0; k < 16; k++)
        v[k] = (v[k] > thr) ? 1.0f : ((v[k] < -thr) ? -1.0f : 0.0f);

    bfly16(v);                              // d bits 0-3
    #pragma unroll
    for (int k = 0; k < 16; k++) s[P16(t * 16 + k)] = v[k];
    __syncthreads();

    const int base = (t & 15) + (t >> 4) * 256;
    #pragma unroll
    for (int k = 0; k < 16; k++) v[k] = s[P16(base + 16 * k)];
    bfly16(v);                              // d bits 4-7
    #pragma unroll
    for (int k = 0; k < 16; k++) s[P16(base + 16 * k)] = v[k];
    __syncthreads();

    #pragma unroll
    for (int k = 0; k < 16; k++) v[k] = s[P16(t + 256 * k)];
    bfly16(v);                              // d bits 8-11
    __half* dst = g_Wh + (size_t)blockIdx.x * DIN;
    #pragma unroll
    for (int k = 0; k < 16; k++) dst[t + 256 * k] = __float2half_rn(v[k]);
}

// ---------- kernel 3: coarse column FWHT_64 over o-bits 6..11, in place on g_Wh ----
__global__ void __launch_bounds__(128) w_colfwht() {
    const int t   = threadIdx.x;
    const int cg  = blockIdx.x;     // 0..31: 128-col group
    const int olo = blockIdx.y;     // 0..63
    __half* base = g_Wh + (size_t)olo * DIN + cg * 128 + t;
    float v[64];
    #pragma unroll
    for (int k = 0; k < 64; k++)
        v[k] = __half2float(base[(size_t)k * 64 * DIN]);
    #pragma unroll
    for (int b = 0; b < 6; b++) {
        const int m = 1 << b;
        #pragma unroll
        for (int k = 0; k < 64; k++) {
            if (!(k & m)) {
                float a = v[k], c = v[k ^ m];
                v[k] = a + c; v[k ^ m] = a - c;
            }
        }
    }
    #pragma unroll
    for (int k = 0; k < 64; k++)
        base[(size_t)k * 64 * DIN] = __float2half_rn(v[k]);
}

// ---------- kernel 4: HMMA GEMM, 8 warps (32x64 tiles), fine FWHT epilogue ----------
__global__ void __launch_bounds__(256, 2) gemm_kernel(float* __restrict__ out) {
    extern __shared__ char smem_raw[];
    const uint32_t data_base = (smem_u32(smem_raw) + 1023u) & ~1023u;
    const int tid = threadIdx.x;
    const int wid = tid >> 5;
    const int lid = tid & 31;
    const int wm = wid >> 1;        // 0..3 (32-row slab)
    const int wn = wid & 1;         // 0..1 (64-col slab)
    const int tileN = blockIdx.x;   // 0..31
    const int tileM = blockIdx.y;   // 0..63

    const char* Ag = (const char*)(g_Xq + (size_t)tileM * TILE_M * DIN);
    const char* Bg = (const char*)(g_Wh + (size_t)tileN * TILE_N * DIN);

    auto load_chunk = [&](int c, int stage) {
        const uint32_t abase = data_base + stage * STAGE_BYTES;
        const uint32_t bbase = abase + A_STAGE_BYTES;
        #pragma unroll
        for (int t = 0; t < 4; t++) {            // A: 128 rows x 8 x 16B
            int idx = tid + t * 256;
            int r = idx >> 3, j = idx & 7;
            uint32_t off = (uint32_t)(r * 128 + j * 16);
            cp16(abase + sw(off), Ag + (size_t)r * (DIN * 2) + c * 128 + j * 16);
        }
        #pragma unroll
        for (int t = 0; t < 4; t++) {            // B: 128 rows x 8 x 16B
            int idx = tid + t * 256;
            int r = idx >> 3, j = idx & 7;
            uint32_t off = (uint32_t)(r * 128 + j * 16);
            cp16(bbase + sw(off), Bg + (size_t)r * (DIN * 2) + c * 128 + j * 16);
        }
    };

    float acc[2][8][4];              // mt(16 rows) x [2*nt+h](8 cols) x quad
    #pragma unroll
    for (int i = 0; i < 2; i++)
        #pragma unroll
        for (int j = 0; j < 8; j++)
            #pragma unroll
            for (int q = 0; q < 4; q++) acc[i][j][q] = 0.f;

    #pragma unroll
    for (int s = 0; s < NSTAGES - 1; s++) {
        load_chunk(s, s);
        asm volatile("cp.async.commit_group;" ::: "memory");
    }

    const uint32_t a_row   = wm * 32 + (lid & 15);
    const uint32_t a_kh    = (uint32_t)(lid >> 4) * 16;
    const uint32_t b_row   = wn * 64 + ((lid >> 4) & 1) * 8 + (lid & 7);
    const uint32_t b_kh    = (uint32_t)((lid >> 3) & 1) * 16;

    int stage = 0;
    for (int c = 0; c < NCHUNK; c++) {
        asm volatile("cp.async.wait_group %0;" :: "n"(1) : "memory");
        __syncthreads();

        const uint32_t abase = data_base + stage * STAGE_BYTES;
        const uint32_t bbase = abase + A_STAGE_BYTES;
        #pragma unroll
        for (int kk = 0; kk < 4; kk++) {
            uint32_t a[2][4];
            #pragma unroll
            for (int mt = 0; mt < 2; mt++) {
                uint32_t off = (a_row + mt * 16) * 128 + kk * 32 + a_kh;
                ldmx4(a[mt], abase + sw(off));
            }
            #pragma unroll
            for (int nt = 0; nt < 4; nt++) {
                uint32_t b[4];
                uint32_t off = (b_row + nt * 16) * 128 + kk * 32 + b_kh;
                ldmx4(b, bbase + sw(off));
                #pragma unroll
                for (int mt = 0; mt < 2; mt++) {
                    mma16816(acc[mt][nt * 2 + 0], a[mt], b[0], b[1]);
                    mma16816(acc[mt][nt * 2 + 1], a[mt], b[2], b[3]);
                }
            }
        }
        if (c + NSTAGES - 1 < NCHUNK) load_chunk(c + NSTAGES - 1, (c + NSTAGES - 1) % NSTAGES);
        asm volatile("cp.async.commit_group;" ::: "memory");
        stage = (stage + 1 == NSTAGES) ? 0 : stage + 1;
    }

    // ---- epilogue: fine FWHT_64 over columns (o-bits 0..5) within this warp ----
    #pragma unroll
    for (int mt = 0; mt < 2; mt++)
        #pragma unroll
        for (int j = 0; j < 8; j++) {
            float a0 = acc[mt][j][0], b0 = acc[mt][j][1];
            acc[mt][j][0] = a0 + b0; acc[mt][j][1] = a0 - b0;
            float a1 = acc[mt][j][2], b1 = acc[mt][j][3];
            acc[mt][j][2] = a1 + b1; acc[mt][j][3] = a1 - b1;
        }
    #pragma unroll
    for (int m = 1; m <= 2; m <<= 1) {
        const bool hi = (lid & m) != 0;
        #pragma unroll
        for (int mt = 0; mt < 2; mt++)
            #pragma unroll
            for (int j = 0; j < 8; j++)
                #pragma unroll
                for (int q = 0; q < 4; q++) {
                    float f = acc[mt][j][q];
                    float t = __shfl_xor_sync(0xFFFFFFFFu, f, m);
                    acc[mt][j][q] = hi ? (t - f) : (f + t);
                }
    }
    #pragma unroll
    for (int m = 1; m <= 4; m <<= 1)
        #pragma unroll
        for (int mt = 0; mt < 2; mt++)
            #pragma unroll
            for (int j = 0; j < 8; j++)
                if (!(j & m))
                    #pragma unroll
                    for (int q = 0; q < 4; q++) {
                        float a = acc[mt][j][q], b = acc[mt][j ^ m][q];
                        acc[mt][j][q] = a + b; acc[mt][j ^ m][q] = a - b;
                    }

    const float sc = g_wscale;
    const int r0 = tileM * TILE_M + wm * 32 + (lid >> 2);
    const int c0 = tileN * TILE_N + wn * 64 + 2 * (lid & 3);
    #pragma unroll
    for (int mt = 0; mt < 2; mt++) {
        float* p = out + (size_t)(r0 + mt * 16) * DIN + c0;
        #pragma unroll
        for (int j = 0; j < 8; j++) {
            *reinterpret_cast<float2*>(p + j * 8) =
                make_float2(acc[mt][j][0] * sc, acc[mt][j][1] * sc);
            *reinterpret_cast<float2*>(p + j * 8 + (size_t)8 * DIN) =
                make_float2(acc[mt][j][2] * sc, acc[mt][j][3] * sc);
        }
    }
}

// ---------- launch ----------
extern "C" void kernel_launch(void* const* d_in, const int* in_sizes, int n_in,
                              void* d_out, int out_size) {
    const float* x     = (const float*)d_in[0];
    const float* gamma = (const float*)d_in[1];
    const float* beta  = (const float*)d_in[2];
    const float* w     = (const float*)d_in[3];
    float* out = (float*)d_out;

    prep1<<<256 + ROWS_X, 512>>>(x, gamma, beta, w);      // launch 0
    w_fwht<<<ROWS_W, 256>>>(w);                           // launch 1
    w_colfwht<<<dim3(32, 64), 128>>>();                   // launch 2
    cudaFuncSetAttribute(gemm_kernel, cudaFuncAttributeMaxDynamicSharedMemorySize, SMEM_GEMM);
    gemm_kernel<<<dim3(32, 64), 256, SMEM_GEMM>>>(out);   // launch 3 (ncu target)
}

// round 17
// speedup vs baseline: 2.9635x; 1.0052x over previous
#include <cuda_runtime.h>
#include <cuda_fp16.h>
#include <stdint.h>

#define DIN      4096
#define ROWS_X   8192
#define ROWS_W   4096
#define NSTAGES  3
#define NCHUNK   64
#define TILE_M   128
#define TILE_N   128
#define A_STAGE_BYTES (TILE_M*128)              // 16 KB
#define B_STAGE_BYTES (TILE_N*128)              // 16 KB
#define STAGE_BYTES   (A_STAGE_BYTES + B_STAGE_BYTES)
#define SMEM_GEMM     (NSTAGES*STAGE_BYTES + 1024)

__device__ __align__(16) __half g_Xq[(size_t)ROWS_X * DIN];   // 64 MB
__device__ __align__(16) __half g_Wh[(size_t)ROWS_W * DIN];   // 32 MB
__device__ float g_partials[256];
__device__ float g_wscale;

// ---------- helpers ----------
static __device__ __forceinline__ uint32_t smem_u32(const void* p) {
    uint32_t a;
    asm("{ .reg .u64 t; cvta.to.shared.u64 t, %1; cvt.u32.u64 %0, t; }" : "=r"(a) : "l"(p));
    return a;
}
static __device__ __forceinline__ void cp16(uint32_t dst, const void* src) {
    asm volatile("cp.async.cg.shared.global [%0], [%1], 16;" :: "r"(dst), "l"(src) : "memory");
}
static __device__ __forceinline__ void ldmx4(uint32_t* r, uint32_t addr) {
    asm volatile("ldmatrix.sync.aligned.m8n8.x4.shared.b16 {%0,%1,%2,%3}, [%4];"
                 : "=r"(r[0]), "=r"(r[1]), "=r"(r[2]), "=r"(r[3]) : "r"(addr));
}
static __device__ __forceinline__ void mma16816(float* d, const uint32_t* a,
                                                uint32_t b0, uint32_t b1) {
    asm volatile(
        "mma.sync.aligned.m16n8k16.row.col.f32.f16.f16.f32 "
        "{%0,%1,%2,%3}, {%4,%5,%6,%7}, {%8,%9}, {%0,%1,%2,%3};"
        : "+f"(d[0]), "+f"(d[1]), "+f"(d[2]), "+f"(d[3])
        : "r"(a[0]), "r"(a[1]), "r"(a[2]), "r"(a[3]), "r"(b0), "r"(b1));
}
static __device__ __forceinline__ uint32_t sw(uint32_t off) {
    return off ^ ((off >> 3) & 0x70);
}

// radix-16 in-register Hadamard butterfly (4 stages on disjoint bits)
static __device__ __forceinline__ void bfly16(float* v) {
    #pragma unroll
    for (int b = 0; b < 4; b++) {
        const int m = 1 << b;
        #pragma unroll
        for (int k = 0; k < 16; k++) {
            if (!(k & m)) {
                float a = v[k], c = v[k ^ m];
                v[k] = a + c; v[k ^ m] = a - c;
            }
        }
    }
}
static __device__ __forceinline__ int P16(int i) { return i + (i >> 4); }

// block-wide max reduction over 512 threads (16 warps)
static __device__ __forceinline__ float block_max(float v, float* red16, int tid) {
    #pragma unroll
    for (int o = 16; o > 0; o >>= 1)
        v = fmaxf(v, __shfl_xor_sync(0xFFFFFFFFu, v, o));
    if ((tid & 31) == 0) red16[tid >> 5] = v;
    __syncthreads();
    float r = red16[0];
    #pragma unroll
    for (int i = 1; i < 16; i++) r = fmaxf(r, red16[i]);
    __syncthreads();
    return r;
}

// fused block-wide sum of TWO values (sum, sumsq) over 512 threads
static __device__ __forceinline__ void block_sum2(float& s, float& q,
                                                  float* redS, float* redQ, int tid) {
    #pragma unroll
    for (int o = 16; o > 0; o >>= 1) {
        s += __shfl_xor_sync(0xFFFFFFFFu, s, o);
        q += __shfl_xor_sync(0xFFFFFFFFu, q, o);
    }
    if ((tid & 31) == 0) { redS[tid >> 5] = s; redQ[tid >> 5] = q; }
    __syncthreads();
    float rs = redS[0], rq = redQ[0];
    #pragma unroll
    for (int i = 1; i < 16; i++) { rs += redS[i]; rq += redQ[i]; }
    __syncthreads();
    s = rs; q = rq;
}

// ---------- kernel 1: fused |w| partials (blocks 0..255) + LayerNorm-quantize ----------
__global__ void __launch_bounds__(512) prep1(const float* __restrict__ x,
                                             const float* __restrict__ gamma,
                                             const float* __restrict__ beta,
                                             const float* __restrict__ w) {
    __shared__ float red[512];
    __shared__ float red16b[16];
    const int tid = threadIdx.x;

    if (blockIdx.x < 256) {
        const size_t s0 = (size_t)blockIdx.x * 65536;
        float s = 0.f;
        for (int i = tid; i < 65536; i += 512) s += fabsf(w[s0 + i]);
        red[tid] = s; __syncthreads();
        #pragma unroll
        for (int o = 256; o > 0; o >>= 1) {
            if (tid < o) red[tid] += red[tid + o];
            __syncthreads();
        }
        if (tid == 0) g_partials[blockIdx.x] = red[0];
        return;
    }

    // ---- LayerNorm + absmax quantize (coalesced, single-pass stats), one row ----
    const int row = blockIdx.x - 256;
    const float* xr = x + (size_t)row * DIN;
    const int ca = tid * 4;
    const int cb = ca + 2048;

    float v[8];
    {
        float4 pa = *reinterpret_cast<const float4*>(xr + ca);
        float4 pb = *reinterpret_cast<const float4*>(xr + cb);
        v[0]=pa.x; v[1]=pa.y; v[2]=pa.z; v[3]=pa.w;
        v[4]=pb.x; v[5]=pb.y; v[6]=pb.z; v[7]=pb.w;
    }
    float s = 0.f, sq = 0.f;
    #pragma unroll
    for (int i = 0; i < 8; i++) { s += v[i]; sq += v[i] * v[i]; }
    block_sum2(s, sq, red, red + 16, tid);
    const float mu = s * (1.0f / DIN);
    const float var = sq * (1.0f / DIN) - mu * mu;   // E[x^2] - mu^2 (no cancellation: mu^2 << E[x^2])
    const float rstd = 1.0f / sqrtf(var + 1e-5f);

    float g[8], b[8];
    {
        float4 ga = *reinterpret_cast<const float4*>(gamma + ca);
        float4 gb = *reinterpret_cast<const float4*>(gamma + cb);
        float4 ba = *reinterpret_cast<const float4*>(beta + ca);
        float4 bb = *reinterpret_cast<const float4*>(beta + cb);
        g[0]=ga.x; g[1]=ga.y; g[2]=ga.z; g[3]=ga.w;
        g[4]=gb.x; g[5]=gb.y; g[6]=gb.z; g[7]=gb.w;
        b[0]=ba.x; b[1]=ba.y; b[2]=ba.z; b[3]=ba.w;
        b[4]=bb.x; b[5]=bb.y; b[6]=bb.z; b[7]=bb.w;
    }

    float y[8];
    float amax = 0.f;
    #pragma unroll
    for (int i = 0; i < 8; i++) {
        y[i] = (v[i] - mu) * rstd * g[i] + b[i];
        amax = fmaxf(amax, fabsf(y[i]));
    }
    const float scale = fminf(fmaxf(block_max(amax, red16b, tid), 1e-6f), 1e6f);
    const float sf = fminf(fmaxf(7.0f / scale, 1e-6f), 1e6f);

    __half h[8];
    #pragma unroll
    for (int i = 0; i < 8; i++) {
        float q = fminf(fmaxf(rintf(y[i] * sf), -7.0f), 7.0f);
        h[i] = __float2half_rn(q);
    }
    __half* dst = g_Xq + (size_t)row * DIN;
    *reinterpret_cast<uint2*>(dst + ca) = *reinterpret_cast<uint2*>(h);
    *reinterpret_cast<uint2*>(dst + cb) = *reinterpret_cast<uint2*>(h + 4);
}

// final reduce of the 256 partials (deterministic tree).
static __device__ __forceinline__ float wscale_from_partials(float* red) {
    const int tid = threadIdx.x;
    if (tid < 256) red[tid] = g_partials[tid];
    __syncthreads();
    #pragma unroll
    for (int o = 128; o > 0; o >>= 1) {
        if (tid < o) red[tid] += red[tid + o];
        __syncthreads();
    }
    return red[0] * (1.0f / 16777216.0f);
}

// ---------- kernel 2: weight ternarize + radix-16 row FWHT (over d) -> fp16 ----------
__global__ void __launch_bounds__(256) w_fwht(const float* __restrict__ w) {
    __shared__ float s[4096 + 256];
    const int t = threadIdx.x;
    const float* wr = w + (size_t)blockIdx.x * DIN;
    const float wscale = wscale_from_partials(s);
    const float thr = 0.5f * wscale;
    if (blockIdx.x == 0 && t == 0) g_wscale = wscale;
    __syncthreads();

    float v[16];
    #pragma unroll
    for (int q = 0; q < 4; q++) {
        float4 p = *reinterpret_cast<const float4*>(wr + t * 16 + q * 4);
        v[q*4+0]=p.x; v[q*4+1]=p.y; v[q*4+2]=p.z; v[q*4+3]=p.w;
    }
    #pragma unroll
    for (int k = 0; k < 16; k++)
        v[k] = (v[k] > thr) ? 1.0f : ((v[k] < -thr) ? -1.0f : 0.0f);

    bfly16(v);                              // d bits 0-3
    #pragma unroll
    for (int k = 0; k < 16; k++) s[P16(t * 16 + k)] = v[k];
    __syncthreads();

    const int base = (t & 15) + (t >> 4) * 256;
    #pragma unroll
    for (int k = 0; k < 16; k++) v[k] = s[P16(base + 16 * k)];
    bfly16(v);                              // d bits 4-7
    #pragma unroll
    for (int k = 0; k < 16; k++) s[P16(base + 16 * k)] = v[k];
    __syncthreads();

    #pragma unroll
    for (int k = 0; k < 16; k++) v[k] = s[P16(t + 256 * k)];
    bfly16(v);                              // d bits 8-11
    __half* dst = g_Wh + (size_t)blockIdx.x * DIN;
    #pragma unroll
    for (int k = 0; k < 16; k++) dst[t + 256 * k] = __float2half_rn(v[k]);
}

// ---------- kernel 3: coarse column FWHT_64 over o-bits 6..11, in place on g_Wh ----
__global__ void __launch_bounds__(128) w_colfwht() {
    const int t   = threadIdx.x;
    const int cg  = blockIdx.x;     // 0..31: 128-col group
    const int olo = blockIdx.y;     // 0..63
    __half* base = g_Wh + (size_t)olo * DIN + cg * 128 + t;
    float v[64];
    #pragma unroll
    for (int k = 0; k < 64; k++)
        v[k] = __half2float(base[(size_t)k * 64 * DIN]);
    #pragma unroll
    for (int b = 0; b < 6; b++) {
        const int m = 1 << b;
        #pragma unroll
        for (int k = 0; k < 64; k++) {
            if (!(k & m)) {
                float a = v[k], c = v[k ^ m];
                v[k] = a + c; v[k ^ m] = a - c;
            }
        }
    }
    #pragma unroll
    for (int k = 0; k < 64; k++)
        base[(size_t)k * 64 * DIN] = __float2half_rn(v[k]);
}

// ---------- kernel 4: HMMA GEMM, 8 warps (32x64 tiles), fine FWHT epilogue ----------
__global__ void __launch_bounds__(256, 2) gemm_kernel(float* __restrict__ out) {
    extern __shared__ char smem_raw[];
    const uint32_t data_base = (smem_u32(smem_raw) + 1023u) & ~1023u;
    const int tid = threadIdx.x;
    const int wid = tid >> 5;
    const int lid = tid & 31;
    const int wm = wid >> 1;        // 0..3 (32-row slab)
    const int wn = wid & 1;         // 0..1 (64-col slab)
    const int tileN = blockIdx.x;   // 0..31
    const int tileM = blockIdx.y;   // 0..63

    const char* Ag = (const char*)(g_Xq + (size_t)tileM * TILE_M * DIN);
    const char* Bg = (const char*)(g_Wh + (size_t)tileN * TILE_N * DIN);

    auto load_chunk = [&](int c, int stage) {
        const uint32_t abase = data_base + stage * STAGE_BYTES;
        const uint32_t bbase = abase + A_STAGE_BYTES;
        #pragma unroll
        for (int t = 0; t < 4; t++) {
            int idx = tid + t * 256;
            int r = idx >> 3, j = idx & 7;
            uint32_t off = (uint32_t)(r * 128 + j * 16);
            cp16(abase + sw(off), Ag + (size_t)r * (DIN * 2) + c * 128 + j * 16);
        }
        #pragma unroll
        for (int t = 0; t < 4; t++) {
            int idx = tid + t * 256;
            int r = idx >> 3, j = idx & 7;
            uint32_t off = (uint32_t)(r * 128 + j * 16);
            cp16(bbase + sw(off), Bg + (size_t)r * (DIN * 2) + c * 128 + j * 16);
        }
    };

    float acc[2][8][4];
    #pragma unroll
    for (int i = 0; i < 2; i++)
        #pragma unroll
        for (int j = 0; j < 8; j++)
            #pragma unroll
            for (int q = 0; q < 4; q++) acc[i][j][q] = 0.f;

    #pragma unroll
    for (int s = 0; s < NSTAGES - 1; s++) {
        load_chunk(s, s);
        asm volatile("cp.async.commit_group;" ::: "memory");
    }

    const uint32_t a_row   = wm * 32 + (lid & 15);
    const uint32_t a_kh    = (uint32_t)(lid >> 4) * 16;
    const uint32_t b_row   = wn * 64 + ((lid >> 4) & 1) * 8 + (lid & 7);
    const uint32_t b_kh    = (uint32_t)((lid >> 3) & 1) * 16;

    int stage = 0;
    for (int c = 0; c < NCHUNK; c++) {
        asm volatile("cp.async.wait_group %0;" :: "n"(1) : "memory");
        __syncthreads();

        const uint32_t abase = data_base + stage * STAGE_BYTES;
        const uint32_t bbase = abase + A_STAGE_BYTES;
        #pragma unroll
        for (int kk = 0; kk < 4; kk++) {
            uint32_t a[2][4];
            #pragma unroll
            for (int mt = 0; mt < 2; mt++) {
                uint32_t off = (a_row + mt * 16) * 128 + kk * 32 + a_kh;
                ldmx4(a[mt], abase + sw(off));
            }
            #pragma unroll
            for (int nt = 0; nt < 4; nt++) {
                uint32_t b[4];
                uint32_t off = (b_row + nt * 16) * 128 + kk * 32 + b_kh;
                ldmx4(b, bbase + sw(off));
                #pragma unroll
                for (int mt = 0; mt < 2; mt++) {
                    mma16816(acc[mt][nt * 2 + 0], a[mt], b[0], b[1]);
                    mma16816(acc[mt][nt * 2 + 1], a[mt], b[2], b[3]);
                }
            }
        }
        if (c + NSTAGES - 1 < NCHUNK) load_chunk(c + NSTAGES - 1, (c + NSTAGES - 1) % NSTAGES);
        asm volatile("cp.async.commit_group;" ::: "memory");
        stage = (stage + 1 == NSTAGES) ? 0 : stage + 1;
    }

    // ---- epilogue: fine FWHT_64 over columns (o-bits 0..5) within this warp ----
    #pragma unroll
    for (int mt = 0; mt < 2; mt++)
        #pragma unroll
        for (int j = 0; j < 8; j++) {
            float a0 = acc[mt][j][0], b0 = acc[mt][j][1];
            acc[mt][j][0] = a0 + b0; acc[mt][j][1] = a0 - b0;
            float a1 = acc[mt][j][2], b1 = acc[mt][j][3];
            acc[mt][j][2] = a1 + b1; acc[mt][j][3] = a1 - b1;
        }
    #pragma unroll
    for (int m = 1; m <= 2; m <<= 1) {
        const bool hi = (lid & m) != 0;
        #pragma unroll
        for (int mt = 0; mt < 2; mt++)
            #pragma unroll
            for (int j = 0; j < 8; j++)
                #pragma unroll
                for (int q = 0; q < 4; q++) {
                    float f = acc[mt][j][q];
                    float t = __shfl_xor_sync(0xFFFFFFFFu, f, m);
                    acc[mt][j][q] = hi ? (t - f) : (f + t);
                }
    }
    #pragma unroll
    for (int m = 1; m <= 4; m <<= 1)
        #pragma unroll
        for (int mt = 0; mt < 2; mt++)
            #pragma unroll
            for (int j = 0; j < 8; j++)
                if (!(j & m))
                    #pragma unroll
                    for (int q = 0; q < 4; q++) {
                        float a = acc[mt][j][q], b = acc[mt][j ^ m][q];
                        acc[mt][j][q] = a + b; acc[mt][j ^ m][q] = a - b;
                    }

    const float sc = g_wscale;
    const int r0 = tileM * TILE_M + wm * 32 + (lid >> 2);
    const int c0 = tileN * TILE_N + wn * 64 + 2 * (lid & 3);
    #pragma unroll
    for (int mt = 0; mt < 2; mt++) {
        float* p = out + (size_t)(r0 + mt * 16) * DIN + c0;
        #pragma unroll
        for (int j = 0; j < 8; j++) {
            *reinterpret_cast<float2*>(p + j * 8) =
                make_float2(acc[mt][j][0] * sc, acc[mt][j][1] * sc);
            *reinterpret_cast<float2*>(p + j * 8 + (size_t)8 * DIN) =
                make_float2(acc[mt][j][2] * sc, acc[mt][j][3] * sc);
        }
    }
}

// ---------- launch ----------
extern "C" void kernel_launch(void* const* d_in, const int* in_sizes, int n_in,
                              void* d_out, int out_size) {
    const float* x     = (const float*)d_in[0];
    const float* gamma = (const float*)d_in[1];
    const float* beta  = (const float*)d_in[2];
    const float* w     = (const float*)d_in[3];
    float* out = (float*)d_out;

    prep1<<<256 + ROWS_X, 512>>>(x, gamma, beta, w);      // launch 0
    w_fwht<<<ROWS_W, 256>>>(w);                           // launch 1
    w_colfwht<<<dim3(32, 64), 128>>>();                   // launch 2
    cudaFuncSetAttribute(gemm_kernel, cudaFuncAttributeMaxDynamicSharedMemorySize, SMEM_GEMM);
    gemm_kernel<<<dim3(32, 64), 256, SMEM_GEMM>>>(out);   // launch 3 (ncu target)
}